// round 1
// baseline (speedup 1.0000x reference)
#include <cuda_runtime.h>
#include <math.h>

// ---------------- problem constants ----------------
#define BATCH 1024
#define NT    8192
#define NS    8192
#define DIM   1024
#define NC    10
#define TEMP  100.0f

// ---------------- scratch (device globals; no allocation) ----------------
__device__ float g_logits[(size_t)BATCH * NT];   // 32 MB, reused for both softmax stages
__device__ float g_xsrc[BATCH * DIM];            // 4 MB
__device__ float g_tn[NT];
__device__ float g_sn[NS];
__device__ float g_xn[BATCH];
__device__ float g_xsn[BATCH];
__device__ float g_t[BATCH * NC];                // preds @ L

// ---------------- row squared-norms ----------------
__global__ void rownorm_kernel(const float* __restrict__ X, float* __restrict__ out, int K) {
    int row = blockIdx.x;
    const float* xr = X + (size_t)row * K;
    float s = 0.f;
    for (int k = threadIdx.x * 4; k < K; k += blockDim.x * 4) {
        float4 v = *reinterpret_cast<const float4*>(xr + k);
        s += v.x * v.x + v.y * v.y + v.z * v.z + v.w * v.w;
    }
    #pragma unroll
    for (int o = 16; o > 0; o >>= 1) s += __shfl_xor_sync(0xffffffffu, s, o);
    __shared__ float ws[8];
    int wid = threadIdx.x >> 5, lid = threadIdx.x & 31;
    if (lid == 0) ws[wid] = s;
    __syncthreads();
    if (threadIdx.x == 0) {
        float t = 0.f;
        for (int i = 0; i < (int)(blockDim.x >> 5); i++) t += ws[i];
        out[row] = t;
    }
}

// ---------------- SGEMM (fp32, single-buffer smem), templated epilogue ----------------
// A: [M,K] row-major.  B: BT ? [N,K] : [K,N] row-major.
// MODE 0: C = A*B          (plain)
// MODE 1: C = -T*sqrt(max(rnA[m]+rnB[n]-2*acc, 1e-12))
// MODE 2: C = -T*(sqrt(...) + sum_c Tm[m,c]*SHL[n,c])
template<int BM, int BN, int BK, int TM, int TN, bool BT, int MODE>
__global__ void __launch_bounds__((BM / TM) * (BN / TN))
gemm_kernel(const float* __restrict__ A, const float* __restrict__ B,
            float* __restrict__ C, int M, int N, int K,
            const float* __restrict__ rnA, const float* __restrict__ rnB,
            const float* __restrict__ Tm, const float* __restrict__ SHL)
{
    constexpr int THREADS = (BM / TM) * (BN / TN);
    constexpr int PAD = 4;
    __shared__ float As[BK][BM + PAD];
    __shared__ float Bs[BK][BN + PAD];

    const int tid = threadIdx.x;
    const int tx = tid % (BN / TN);
    const int ty = tid / (BN / TN);
    const int row0 = blockIdx.y * BM;
    const int col0 = blockIdx.x * BN;

    float acc[TM][TN];
    #pragma unroll
    for (int i = 0; i < TM; i++)
        #pragma unroll
        for (int j = 0; j < TN; j++) acc[i][j] = 0.f;

    // A tile load mapping: float4 along K
    constexpr int AK4 = BK / 4;
    const int a_r = tid / AK4;
    const int a_c = (tid % AK4) * 4;
    constexpr int A_IT = THREADS / AK4;

    // B tile load mappings
    constexpr int BK4 = BK / 4;       // for BT (B is [N,K])
    const int bt_r = tid / BK4;
    const int bt_c = (tid % BK4) * 4;
    constexpr int BT_IT = THREADS / BK4;

    constexpr int BN4 = BN / 4;       // for !BT (B is [K,N])
    const int bn_r = tid / BN4;
    const int bn_c = (tid % BN4) * 4;
    constexpr int BNR_IT = THREADS / BN4;

    for (int k0 = 0; k0 < K; k0 += BK) {
        // load A tile (transpose into As[k][m])
        #pragma unroll
        for (int it = 0; it < BM / A_IT; it++) {
            int r = a_r + it * A_IT;
            float4 v = *reinterpret_cast<const float4*>(A + (size_t)(row0 + r) * K + (k0 + a_c));
            As[a_c + 0][r] = v.x; As[a_c + 1][r] = v.y;
            As[a_c + 2][r] = v.z; As[a_c + 3][r] = v.w;
        }
        if (BT) {
            #pragma unroll
            for (int it = 0; it < BN / BT_IT; it++) {
                int r = bt_r + it * BT_IT;
                float4 v = *reinterpret_cast<const float4*>(B + (size_t)(col0 + r) * K + (k0 + bt_c));
                Bs[bt_c + 0][r] = v.x; Bs[bt_c + 1][r] = v.y;
                Bs[bt_c + 2][r] = v.z; Bs[bt_c + 3][r] = v.w;
            }
        } else {
            #pragma unroll
            for (int it = 0; it < BK / BNR_IT; it++) {
                int r = bn_r + it * BNR_IT;
                float4 v = *reinterpret_cast<const float4*>(B + (size_t)(k0 + r) * N + (col0 + bn_c));
                *reinterpret_cast<float4*>(&Bs[r][bn_c]) = v;
            }
        }
        __syncthreads();
        #pragma unroll
        for (int kk = 0; kk < BK; kk++) {
            float af[TM], bf[TN];
            #pragma unroll
            for (int i = 0; i < TM; i += 4)
                *reinterpret_cast<float4*>(&af[i]) =
                    *reinterpret_cast<const float4*>(&As[kk][ty * TM + i]);
            #pragma unroll
            for (int j = 0; j < TN; j += 4)
                *reinterpret_cast<float4*>(&bf[j]) =
                    *reinterpret_cast<const float4*>(&Bs[kk][tx * TN + j]);
            #pragma unroll
            for (int i = 0; i < TM; i++)
                #pragma unroll
                for (int j = 0; j < TN; j++)
                    acc[i][j] = fmaf(af[i], bf[j], acc[i][j]);
        }
        __syncthreads();
    }

    // ---------------- epilogue ----------------
    if (MODE == 0) {
        #pragma unroll
        for (int i = 0; i < TM; i++) {
            int gm = row0 + ty * TM + i;
            #pragma unroll
            for (int j = 0; j < TN; j += 4) {
                float4 v = make_float4(acc[i][j], acc[i][j + 1], acc[i][j + 2], acc[i][j + 3]);
                *reinterpret_cast<float4*>(&C[(size_t)gm * N + (col0 + tx * TN + j)]) = v;
            }
        }
    } else {
        float ra[TM];
        #pragma unroll
        for (int i = 0; i < TM; i++) ra[i] = __ldg(&rnA[row0 + ty * TM + i]);
        #pragma unroll
        for (int j = 0; j < TN; j++) {
            int gn = col0 + tx * TN + j;
            float rb = __ldg(&rnB[gn]);
            float sv[NC];
            if (MODE == 2) {
                #pragma unroll
                for (int c = 0; c < NC; c++) sv[c] = __ldg(&SHL[(size_t)gn * NC + c]);
            }
            #pragma unroll
            for (int i = 0; i < TM; i++) {
                int gm = row0 + ty * TM + i;
                float sq = ra[i] + rb - 2.f * acc[i][j];
                float d = sqrtf(fmaxf(sq, 1e-12f));
                if (MODE == 2) {
                    float lab = 0.f;
                    #pragma unroll
                    for (int c = 0; c < NC; c++)
                        lab = fmaf(__ldg(&Tm[gm * NC + c]), sv[c], lab);
                    d += lab;
                }
                C[(size_t)gm * N + gn] = -TEMP * d;
            }
        }
    }
}

// ---------------- in-place row softmax (rows of length NCOL) ----------------
template<int NCOL, int THREADS>
__global__ void softmax_rows_kernel(float* __restrict__ X) {
    constexpr int PER = NCOL / THREADS;
    int row = blockIdx.x;
    float* xr = X + (size_t)row * NCOL;
    int tid = threadIdx.x;
    float r[PER];
    float mx = -INFINITY;
    #pragma unroll
    for (int i = 0; i < PER; i++) {
        r[i] = xr[tid + i * THREADS];
        mx = fmaxf(mx, r[i]);
    }
    __shared__ float sred[THREADS / 32];
    // block max
    #pragma unroll
    for (int o = 16; o > 0; o >>= 1) mx = fmaxf(mx, __shfl_xor_sync(0xffffffffu, mx, o));
    if ((tid & 31) == 0) sred[tid >> 5] = mx;
    __syncthreads();
    {
        float m = sred[0];
        #pragma unroll
        for (int i = 1; i < THREADS / 32; i++) m = fmaxf(m, sred[i]);
        mx = m;
    }
    __syncthreads();
    float s = 0.f;
    #pragma unroll
    for (int i = 0; i < PER; i++) {
        r[i] = expf(r[i] - mx);
        s += r[i];
    }
    #pragma unroll
    for (int o = 16; o > 0; o >>= 1) s += __shfl_xor_sync(0xffffffffu, s, o);
    if ((tid & 31) == 0) sred[tid >> 5] = s;
    __syncthreads();
    {
        float m = 0.f;
        #pragma unroll
        for (int i = 0; i < THREADS / 32; i++) m += sred[i];
        s = m;
    }
    float inv = 1.f / s;
    #pragma unroll
    for (int i = 0; i < PER; i++) xr[tid + i * THREADS] = r[i] * inv;
}

// ---------------- classifier head: preds = softmax(xsrc@W+b); t = preds@L; xsn ----------------
__global__ void preds_kernel(const float* __restrict__ xsrc, const float* __restrict__ W,
                             const float* __restrict__ b, const float* __restrict__ L,
                             float* __restrict__ t_out, float* __restrict__ xsn)
{
    int row = blockIdx.x;
    int tid = threadIdx.x;
    const float* xr = xsrc + (size_t)row * DIM;
    float acc[NC];
    #pragma unroll
    for (int c = 0; c < NC; c++) acc[c] = 0.f;
    float nrm = 0.f;
    for (int k = tid; k < DIM; k += blockDim.x) {
        float xv = xr[k];
        nrm = fmaf(xv, xv, nrm);
        #pragma unroll
        for (int c = 0; c < NC; c++) acc[c] = fmaf(xv, __ldg(&W[k * NC + c]), acc[c]);
    }
    __shared__ float red[NC + 1][128];
    #pragma unroll
    for (int c = 0; c < NC; c++) red[c][tid] = acc[c];
    red[NC][tid] = nrm;
    __syncthreads();
    for (int st = 64; st > 0; st >>= 1) {
        if (tid < st) {
            #pragma unroll
            for (int c = 0; c <= NC; c++) red[c][tid] += red[c][tid + st];
        }
        __syncthreads();
    }
    if (tid == 0) {
        float lg[NC], m = -INFINITY, s = 0.f;
        #pragma unroll
        for (int c = 0; c < NC; c++) { lg[c] = red[c][0] + b[c]; m = fmaxf(m, lg[c]); }
        #pragma unroll
        for (int c = 0; c < NC; c++) { lg[c] = expf(lg[c] - m); s += lg[c]; }
        float inv = 1.f / s;
        #pragma unroll
        for (int c = 0; c < NC; c++) {
            float tv = 0.f;
            #pragma unroll
            for (int cc = 0; cc < NC; cc++) tv = fmaf(lg[cc] * inv, L[cc * NC + c], tv);
            t_out[row * NC + c] = tv;
        }
        xsn[row] = red[NC][0];
    }
}

// ---------------- fused softmax + (w @ atl) -> y [BATCH, NC] ----------------
__global__ void final_kernel(const float* __restrict__ logits, const float* __restrict__ atl,
                             float* __restrict__ y)
{
    constexpr int THREADS = 256;
    constexpr int PER = NS / THREADS;  // 32
    int row = blockIdx.x;
    int tid = threadIdx.x;
    const float* xr = logits + (size_t)row * NS;
    float r[PER];
    float mx = -INFINITY;
    #pragma unroll
    for (int i = 0; i < PER; i++) {
        r[i] = xr[tid + i * THREADS];
        mx = fmaxf(mx, r[i]);
    }
    __shared__ float sred[THREADS / 32];
    #pragma unroll
    for (int o = 16; o > 0; o >>= 1) mx = fmaxf(mx, __shfl_xor_sync(0xffffffffu, mx, o));
    if ((tid & 31) == 0) sred[tid >> 5] = mx;
    __syncthreads();
    {
        float m = sred[0];
        #pragma unroll
        for (int i = 1; i < THREADS / 32; i++) m = fmaxf(m, sred[i]);
        mx = m;
    }
    __syncthreads();

    float s = 0.f;
    float ya[NC];
    #pragma unroll
    for (int c = 0; c < NC; c++) ya[c] = 0.f;
    #pragma unroll
    for (int i = 0; i < PER; i++) {
        float e = expf(r[i] - mx);
        s += e;
        int j = tid + i * THREADS;
        const float* a = atl + (size_t)j * NC;
        #pragma unroll
        for (int c = 0; c < NC; c++) ya[c] = fmaf(e, __ldg(&a[c]), ya[c]);
    }
    __shared__ float red[NC + 1][THREADS];
    #pragma unroll
    for (int c = 0; c < NC; c++) red[c][tid] = ya[c];
    red[NC][tid] = s;
    __syncthreads();
    for (int st = THREADS / 2; st > 0; st >>= 1) {
        if (tid < st) {
            #pragma unroll
            for (int c = 0; c <= NC; c++) red[c][tid] += red[c][tid + st];
        }
        __syncthreads();
    }
    if (tid < NC) {
        y[row * NC + tid] = red[tid][0] / red[NC][0];
    }
}

// ---------------- launch ----------------
extern "C" void kernel_launch(void* const* d_in, const int* in_sizes, int n_in,
                              void* d_out, int out_size)
{
    const float* x   = (const float*)d_in[0];  // [B,32,32]
    const float* tf  = (const float*)d_in[1];  // [Nt,32,32]
    const float* asf = (const float*)d_in[2];  // [Nt,32,32]
    const float* sf  = (const float*)d_in[3];  // [Ns,32,32]
    const float* shl = (const float*)d_in[4];  // [Ns,C]
    const float* atl = (const float*)d_in[5];  // [Ns,C]
    const float* sld = (const float*)d_in[6];  // [C,C]
    const float* W   = (const float*)d_in[7];  // [D,C]
    const float* b   = (const float*)d_in[8];  // [C]
    float* y = (float*)d_out;                  // [B,C]

    float *logits, *xsrc, *tn, *sn, *xn, *xsn, *tbuf;
    cudaGetSymbolAddress((void**)&logits, g_logits);
    cudaGetSymbolAddress((void**)&xsrc,   g_xsrc);
    cudaGetSymbolAddress((void**)&tn,     g_tn);
    cudaGetSymbolAddress((void**)&sn,     g_sn);
    cudaGetSymbolAddress((void**)&xn,     g_xn);
    cudaGetSymbolAddress((void**)&xsn,    g_xsn);
    cudaGetSymbolAddress((void**)&tbuf,   g_t);

    // 1) row norms
    rownorm_kernel<<<NT, 256>>>(tf, tn, DIM);
    rownorm_kernel<<<NS, 256>>>(sf, sn, DIM);
    rownorm_kernel<<<BATCH, 256>>>(x, xn, DIM);

    // 2) feature-transport logits: -T * cdist(xf, tf)
    gemm_kernel<128, 128, 16, 8, 8, true, 1>
        <<<dim3(NT / 128, BATCH / 128), 256>>>(
            x, tf, logits, BATCH, NT, DIM, xn, tn, nullptr, nullptr);

    // 3) softmax over Nt
    softmax_rows_kernel<NT, 256><<<BATCH, 256>>>(logits);

    // 4) x_src = w_feat @ asf
    gemm_kernel<128, 64, 16, 8, 4, false, 0>
        <<<dim3(DIM / 64, BATCH / 128), 256>>>(
            logits, asf, xsrc, BATCH, DIM, NT, nullptr, nullptr, nullptr, nullptr);

    // 5) classifier head -> t = preds @ L, and ||x_src||^2
    preds_kernel<<<BATCH, 128>>>(xsrc, W, b, sld, tbuf, xsn);

    // 6) label-transport logits: -T * (cdist(x_src, sf) + t @ shl^T)
    gemm_kernel<128, 128, 16, 8, 8, true, 2>
        <<<dim3(NS / 128, BATCH / 128), 256>>>(
            xsrc, sf, logits, BATCH, NS, DIM, xsn, sn, tbuf, shl);

    // 7) softmax over Ns fused with y = w_lab @ atl
    final_kernel<<<BATCH, 256>>>(logits, atl, y);
}